// round 16
// baseline (speedup 1.0000x reference)
#include <cuda_runtime.h>
#include <cuda_fp16.h>
#include <math.h>
#include <stdint.h>

// Problem constants
#define BB 32
#define CC 64
#define VV 1024
#define TT 24
#define COUT 64
#define MROWS (BB*CC)            // 2048
#define PART ((size_t)MROWS*VV)  // 2,097,152
#define CVSZ (CC*VV)             // 65536

// ---------------------------------------------------------------------------
__device__ __forceinline__ uint32_t smem_to_u32(const void* p) {
    uint32_t a;
    asm("{ .reg .u64 t; cvta.to.shared.u64 t, %1; cvt.u32.u64 %0, t; }" : "=r"(a) : "l"(p));
    return a;
}
__device__ __forceinline__ void cpasync16(uint32_t dst, const void* src) {
    asm volatile("cp.async.cg.shared.global [%0], [%1], 16;" :: "r"(dst), "l"(src));
}
#define CP_COMMIT() asm volatile("cp.async.commit_group;" ::: "memory")
#define CP_WAIT(n)  asm volatile("cp.async.wait_group %0;" :: "n"(n) : "memory")

__device__ __forceinline__ void ldsm_x4(uint32_t* r, uint32_t a) {
    asm volatile("ldmatrix.sync.aligned.m8n8.x4.shared.b16 {%0,%1,%2,%3}, [%4];"
                 : "=r"(r[0]), "=r"(r[1]), "=r"(r[2]), "=r"(r[3]) : "r"(a));
}
__device__ __forceinline__ void ldsm_x4_trans(uint32_t* r, uint32_t a) {
    asm volatile("ldmatrix.sync.aligned.m8n8.x4.trans.shared.b16 {%0,%1,%2,%3}, [%4];"
                 : "=r"(r[0]), "=r"(r[1]), "=r"(r[2]), "=r"(r[3]) : "r"(a));
}

// m16n8k16 row.col fp16 -> fp32 accumulate
__device__ __forceinline__ void mma16816(float* c, const uint32_t* a, const uint32_t* b) {
    asm volatile(
        "mma.sync.aligned.m16n8k16.row.col.f32.f16.f16.f32 "
        "{%0,%1,%2,%3}, {%4,%5,%6,%7}, {%8,%9}, {%0,%1,%2,%3};"
        : "+f"(c[0]), "+f"(c[1]), "+f"(c[2]), "+f"(c[3])
        : "r"(a[0]), "r"(a[1]), "r"(a[2]), "r"(a[3]), "r"(b[0]), "r"(b[1]));
}

__device__ __forceinline__ float sigf(float x) { return 1.0f / (1.0f + __expf(-x)); }
__device__ __forceinline__ float tanh_fast(float x) {
    float y; asm("tanh.approx.f32 %0, %1;" : "=f"(y) : "f"(x)); return y;
}
__device__ __forceinline__ uint32_t packh2(float a, float b) {
    return ((uint32_t)__half_as_ushort(__float2half_rn(b)) << 16) |
           (uint32_t)__half_as_ushort(__float2half_rn(a));
}
__device__ __forceinline__ float h2f(float a) {
    return __half2float(__float2half_rn(a));
}

// ---------------------------------------------------------------------------
// Scratch
__device__ __align__(128) float g_xT[(size_t)TT*MROWS*VV];
__device__ __align__(128) float g_ys[(size_t)TT*MROWS*VV];
__device__ __align__(128) float g_c[(size_t)MROWS*VV];
__device__ __align__(128) __half g_comb[(size_t)MROWS*VV];   // single fp16 plane
__device__ __align__(128) __half g_x1[(size_t)MROWS*VV];
__device__ __align__(128) __half g_x2[(size_t)MROWS*VV];
// B2 = [A^T ; (A^2)^T] fp16 hi (step hop uses hi ONLY), lo (setup only, rows 0..1023)
__device__ __align__(128) __half g_Bhi[(size_t)2*VV*VV];
__device__ __align__(128) __half g_Blo[(size_t)2*VV*VV];
// A row-major fp16 hi/lo (setup only)
__device__ __align__(128) __half g_Armhi[(size_t)VV*VV];
__device__ __align__(128) __half g_Armlo[(size_t)VV*VV];
// W prepacked per-lane mma A-fragments fp16 (hi only used by gate)
__device__ __align__(128) uint4 g_WfHi[16*12*32];

// ---------------------------------------------------------------------------
__global__ void transpose_x(const float* __restrict__ x) {
    __shared__ float tile[32][25];
    int r  = blockIdx.x;
    int v0 = blockIdx.y * 32;
    const float* src = x + ((size_t)r * VV + v0) * TT;
    for (int i = threadIdx.x; i < 32 * TT; i += blockDim.x) {
        int v = i / TT, t = i % TT;
        tile[v][t] = src[i];
    }
    __syncthreads();
    for (int i = threadIdx.x; i < 32 * TT; i += blockDim.x) {
        int t = i / 32, v = i % 32;
        g_xT[(size_t)t * PART + (size_t)r * VV + v0 + v] = tile[v][t];
    }
}

__global__ void zero_c() {
    size_t i = (size_t)blockIdx.x * blockDim.x + threadIdx.x;
    g_c[i] = 0.0f;
}

// Bhi/Blo[n][k] = fp16split(A[k][n])  (rows 0..1023 of B2)
__global__ void bsplit(const float* __restrict__ A) {
    __shared__ float tile[32][33];
    int k0 = blockIdx.x * 32, n0 = blockIdx.y * 32;
    int tx = threadIdx.x & 31, ty = threadIdx.x >> 5;
    #pragma unroll
    for (int i = 0; i < 4; i++) {
        int k = ty + i * 8;
        tile[k][tx] = A[(size_t)(k0 + k) * VV + n0 + tx];
    }
    __syncthreads();
    #pragma unroll
    for (int i = 0; i < 4; i++) {
        int n = ty + i * 8;
        float v = tile[tx][n];
        __half h = __float2half_rn(v);
        __half l = __float2half_rn(v - __half2float(h));
        g_Bhi[(size_t)(n0 + n) * VV + k0 + tx] = h;
        g_Blo[(size_t)(n0 + n) * VV + k0 + tx] = l;
    }
}

// A row-major fp16 hi/lo
__global__ void asplit(const float* __restrict__ A) {
    size_t i = ((size_t)blockIdx.x * blockDim.x + threadIdx.x) * 4;
    float4 v = *reinterpret_cast<const float4*>(A + i);
    *reinterpret_cast<uint2*>(g_Armhi + i) =
        make_uint2(packh2(v.x, v.y), packh2(v.z, v.w));
    *reinterpret_cast<uint2*>(g_Armlo + i) =
        make_uint2(packh2(v.x - h2f(v.x), v.y - h2f(v.y)),
                   packh2(v.z - h2f(v.z), v.w - h2f(v.w)));
}

// Prepack W into per-lane mma A-fragments (fp16 hi plane).
__global__ void wfrag(const float* __restrict__ W) {
    int tile = blockIdx.x;
    int lane = threadIdx.x;
    int tileM = tile / 12, tileK = tile % 12;
    int r = lane >> 2, c2 = (lane & 3) * 2;

    auto getw = [&](int pr, int k) -> float {
        int wm = pr >> 6, g = (pr >> 4) & 3, cl = pr & 15;
        int o = g * 64 + wm * 16 + cl;
        return W[(size_t)o * 192 + k];
    };
    int p0 = tileM * 16 + r, k0 = tileK * 16 + c2;
    float w[4][2];
    w[0][0] = getw(p0,     k0);     w[0][1] = getw(p0,     k0 + 1);
    w[1][0] = getw(p0 + 8, k0);     w[1][1] = getw(p0 + 8, k0 + 1);
    w[2][0] = getw(p0,     k0 + 8); w[2][1] = getw(p0,     k0 + 9);
    w[3][0] = getw(p0 + 8, k0 + 8); w[3][1] = getw(p0 + 8, k0 + 9);

    uint32_t hi[4];
    #pragma unroll
    for (int q = 0; q < 4; q++)
        hi[q] = packh2(w[q][0], w[q][1]);
    g_WfHi[tile * 32 + lane] = make_uint4(hi[0], hi[1], hi[2], hi[3]);
}

// comb init for t=0: comb = x0 (h = 0), single fp16 plane
__global__ void comb_init(const float* __restrict__ xt) {
    size_t i = ((size_t)blockIdx.x * blockDim.x + threadIdx.x) * 4;
    float4 v = *reinterpret_cast<const float4*>(xt + i);
    *reinterpret_cast<uint2*>(g_comb + i) =
        make_uint2(packh2(v.x, v.y), packh2(v.z, v.w));
}

// ---------------------------------------------------------------------------
// Setup GEMM (A^2 precompute) — fp16 split-3, writes hi/lo output.
#define ROWB 80
#define HPLANE (128*ROWB)            // 10240
#define HBUF4 (4*HPLANE)             // 40960
#define SETUP_SMEM (2*HBUF4)         // 81920

__global__ __launch_bounds__(256, 1) void hop_setup(
    const __half* __restrict__ Ahi, const __half* __restrict__ Alo,
    const __half* __restrict__ Bhi, const __half* __restrict__ Blo,
    __half* __restrict__ Chi, __half* __restrict__ Clo)
{
    extern __shared__ char smem[];
    uint32_t sb = smem_to_u32(smem);
    const int tid = threadIdx.x, lane = tid & 31, wid = tid >> 5;
    const int wm = wid & 3, wn = wid >> 2;
    const int m0 = blockIdx.y * 128, n0 = blockIdx.x * 128;
    const int lr  = lane >> 2;

    float acc[2][8][4];
    #pragma unroll
    for (int mt = 0; mt < 2; mt++)
        #pragma unroll
        for (int nt = 0; nt < 8; nt++)
            #pragma unroll
            for (int q = 0; q < 4; q++) acc[mt][nt][q] = 0.f;

    const int gr = tid >> 2, gc = tid & 3;

    auto load_chunk = [&](int k0, uint32_t base) {
        #pragma unroll
        for (int it = 0; it < 2; it++) {
            int row = gr + it * 64;
            uint32_t doff = (uint32_t)(row * ROWB + gc * 16);
            size_t ga = (((size_t)(m0 + row)) << 10) + k0 + gc * 8;
            size_t gb = (((size_t)(n0 + row)) << 10) + k0 + gc * 8;
            cpasync16(base + doff,              Ahi + ga);
            cpasync16(base + HPLANE + doff,     Alo + ga);
            cpasync16(base + 2 * HPLANE + doff, Bhi + gb);
            cpasync16(base + 3 * HPLANE + doff, Blo + gb);
        }
        CP_COMMIT();
    };

    load_chunk(0, sb);

    const uint32_t aRowSel = (uint32_t)(lane & 15);
    const uint32_t aColSel = (uint32_t)((lane >> 4) * 16);
    const uint32_t bRowSel = (uint32_t)(((lane >> 4) << 3) + (lane & 7));
    const uint32_t bColSel = (uint32_t)(((lane >> 3) & 1) * 16);

    for (int chunk = 0; chunk < 32; chunk++) {
        uint32_t base = sb + (chunk & 1) * HBUF4;
        if (chunk + 1 < 32) {
            load_chunk((chunk + 1) * 32, sb + ((chunk + 1) & 1) * HBUF4);
            CP_WAIT(1);
        } else {
            CP_WAIT(0);
        }
        __syncthreads();

        uint32_t aB = base + (uint32_t)(wm * 32) * ROWB;
        uint32_t bB = base + 2 * HPLANE + (uint32_t)(wn * 64) * ROWB;
        #pragma unroll
        for (int ks = 0; ks < 2; ks++) {
            uint32_t koff = (uint32_t)(ks * 32);
            uint32_t ah[2][4], al[2][4];
            #pragma unroll
            for (int mt = 0; mt < 2; mt++) {
                uint32_t a = aB + (uint32_t)(mt * 16 + aRowSel) * ROWB + koff + aColSel;
                ldsm_x4(ah[mt], a);
                ldsm_x4(al[mt], a + HPLANE);
            }
            #pragma unroll
            for (int h = 0; h < 4; h++) {
                uint32_t a = bB + (uint32_t)(h * 16 + bRowSel) * ROWB + koff + bColSel;
                uint32_t rh[4], rl[4];
                ldsm_x4(rh, a);
                ldsm_x4(rl, a + HPLANE);
                uint32_t b0h[2] = {rh[0], rh[1]}, b1h[2] = {rh[2], rh[3]};
                uint32_t b0l[2] = {rl[0], rl[1]}, b1l[2] = {rl[2], rl[3]};
                #pragma unroll
                for (int mt = 0; mt < 2; mt++) {
                    mma16816(acc[mt][2*h],   ah[mt], b0h);
                    mma16816(acc[mt][2*h],   ah[mt], b0l);
                    mma16816(acc[mt][2*h],   al[mt], b0h);
                    mma16816(acc[mt][2*h+1], ah[mt], b1h);
                    mma16816(acc[mt][2*h+1], ah[mt], b1l);
                    mma16816(acc[mt][2*h+1], al[mt], b1h);
                }
            }
        }
        __syncthreads();
    }

    #pragma unroll
    for (int mt = 0; mt < 2; mt++) {
        int row = m0 + wm * 32 + mt * 16 + lr;
        #pragma unroll
        for (int nt = 0; nt < 8; nt++) {
            int col = n0 + wn * 64 + nt * 8 + (lane & 3) * 2;
            float v0 = acc[mt][nt][0], v1 = acc[mt][nt][1];
            float v2 = acc[mt][nt][2], v3 = acc[mt][nt][3];
            size_t o0 = (size_t)row * 1024 + col;
            size_t o1 = (size_t)(row + 8) * 1024 + col;
            *reinterpret_cast<uint32_t*>(Chi + o0) = packh2(v0, v1);
            *reinterpret_cast<uint32_t*>(Chi + o1) = packh2(v2, v3);
            *reinterpret_cast<uint32_t*>(Clo + o0) = packh2(v0 - h2f(v0), v1 - h2f(v1));
            *reinterpret_cast<uint32_t*>(Clo + o1) = packh2(v2 - h2f(v2), v3 - h2f(v3));
        }
    }
}

// ---------------------------------------------------------------------------
// Step hop GEMM: [x1|x2] = comb(fp16) @ B2hi(fp16) — single product.
// 3-stage cp.async pipeline; 2 CTAs/SM.
#define SBUF (2*HPLANE)              // 20480: [A | Bhi]
#define HOP_SMEM (3*SBUF)            // 61440

__global__ __launch_bounds__(256, 2) void hop_step()
{
    extern __shared__ char smem[];
    uint32_t sb = smem_to_u32(smem);
    const int tid = threadIdx.x, lane = tid & 31, wid = tid >> 5;
    const int wm = wid & 3, wn = wid >> 2;          // warp tile: M32 x N64
    const int m0 = blockIdx.y * 128, n0 = blockIdx.x * 128;  // n over 2048
    const int lr  = lane >> 2;

    float acc[2][8][4];
    #pragma unroll
    for (int mt = 0; mt < 2; mt++)
        #pragma unroll
        for (int nt = 0; nt < 8; nt++)
            #pragma unroll
            for (int q = 0; q < 4; q++) acc[mt][nt][q] = 0.f;

    const int gr = tid >> 2, gc = tid & 3;

    auto load_chunk = [&](int k0, uint32_t base) {
        #pragma unroll
        for (int it = 0; it < 2; it++) {
            int row = gr + it * 64;
            uint32_t doff = (uint32_t)(row * ROWB + gc * 16);
            size_t ga = (((size_t)(m0 + row)) << 10) + k0 + gc * 8;
            size_t gb = (((size_t)(n0 + row)) << 10) + k0 + gc * 8;
            cpasync16(base + doff,          g_comb + ga);
            cpasync16(base + HPLANE + doff, g_Bhi + gb);
        }
        CP_COMMIT();
    };

    // 3-stage: two chunks in flight ahead of compute
    load_chunk(0, sb);
    load_chunk(32, sb + SBUF);

    const uint32_t aRowSel = (uint32_t)(lane & 15);
    const uint32_t aColSel = (uint32_t)((lane >> 4) * 16);
    const uint32_t bRowSel = (uint32_t)(((lane >> 4) << 3) + (lane & 7));
    const uint32_t bColSel = (uint32_t)(((lane >> 3) & 1) * 16);

    int bufc = 0;                                  // buffer index of current chunk
    for (int chunk = 0; chunk < 32; chunk++) {
        uint32_t base = sb + (uint32_t)(bufc * SBUF);
        if (chunk + 2 < 32) {
            int bufn = bufc + 2; if (bufn >= 3) bufn -= 3;
            load_chunk((chunk + 2) * 32, sb + (uint32_t)(bufn * SBUF));
            CP_WAIT(2);
        } else if (chunk + 1 < 32) {
            CP_WAIT(1);
        } else {
            CP_WAIT(0);
        }
        __syncthreads();

        uint32_t aB = base + (uint32_t)(wm * 32) * ROWB;
        uint32_t bB = base + HPLANE + (uint32_t)(wn * 64) * ROWB;
        #pragma unroll
        for (int ks = 0; ks < 2; ks++) {
            uint32_t koff = (uint32_t)(ks * 32);
            uint32_t ah[2][4];
            #pragma unroll
            for (int mt = 0; mt < 2; mt++) {
                uint32_t a = aB + (uint32_t)(mt * 16 + aRowSel) * ROWB + koff + aColSel;
                ldsm_x4(ah[mt], a);
            }
            #pragma unroll
            for (int h = 0; h < 4; h++) {
                uint32_t a = bB + (uint32_t)(h * 16 + bRowSel) * ROWB + koff + bColSel;
                uint32_t rh[4];
                ldsm_x4(rh, a);
                uint32_t b0h[2] = {rh[0], rh[1]}, b1h[2] = {rh[2], rh[3]};
                #pragma unroll
                for (int mt = 0; mt < 2; mt++) {
                    mma16816(acc[mt][2*h],   ah[mt], b0h);
                    mma16816(acc[mt][2*h+1], ah[mt], b1h);
                }
            }
        }
        __syncthreads();
        if (++bufc >= 3) bufc = 0;
    }

    // Epilogue: single fp16 plane; n0<1024 -> x1, else x2
    __half* Cout = (n0 < 1024) ? g_x1 : g_x2;
    const int nb = n0 & 1023;
    #pragma unroll
    for (int mt = 0; mt < 2; mt++) {
        int row = m0 + wm * 32 + mt * 16 + lr;
        #pragma unroll
        for (int nt = 0; nt < 8; nt++) {
            int col = nb + wn * 64 + nt * 8 + (lane & 3) * 2;
            size_t o0 = (size_t)row * 1024 + col;
            size_t o1 = (size_t)(row + 8) * 1024 + col;
            *reinterpret_cast<uint32_t*>(Cout + o0) = packh2(acc[mt][nt][0], acc[mt][nt][1]);
            *reinterpret_cast<uint32_t*>(Cout + o1) = packh2(acc[mt][nt][2], acc[mt][nt][3]);
        }
    }
}

// ---------------------------------------------------------------------------
// Gate GEMM (W hi-only fp16 frags x G single fp16) + LSTM + comb_{t+1}.
// Progressive plane loading: MMA on plane p starts as soon as group p lands.
#define RKG 144
#define GATE_SMEM (192*RKG)          // 27648

__global__ __launch_bounds__(256, 2) void gate_lstm(
    const float* __restrict__ bias, float* __restrict__ ysOut,
    const float* __restrict__ xnext)
{
    extern __shared__ char smem[];
    uint32_t sb = smem_to_u32(smem);
    const int tid = threadIdx.x, lane = tid & 31, wid = tid >> 5;
    const int wm = wid & 3, wn = wid >> 2;       // warp tile M64 x N32
    const int v0 = blockIdx.x * 64;
    const int b  = blockIdx.y;
    const int grp = lane >> 3, lr8 = lane & 7;

    float acc[4][4][4];
    #pragma unroll
    for (int mt = 0; mt < 4; mt++)
        #pragma unroll
        for (int nt = 0; nt < 4; nt++)
            #pragma unroll
            for (int q = 0; q < 4; q++) acc[mt][nt][q] = 0.f;

    // Issue three commit groups: comb rows 0-63, x1 rows 64-127, x2 rows 128-191
    {
        #pragma unroll
        for (int p = 0; p < 3; p++) {
            const __half* src = (p == 0) ? g_comb : (p == 1) ? g_x1 : g_x2;
            #pragma unroll
            for (int j = 0; j < 2; j++) {
                int idx = tid + j * 256;           // 0..511
                int row = idx >> 3, i8 = idx & 7;  // row 0..63
                size_t gsrc = (((size_t)(b * 64 + row)) << 10) + v0 + i8 * 8;
                cpasync16(sb + (uint32_t)((p * 64 + row) * RKG + i8 * 16), src + gsrc);
            }
            CP_COMMIT();
        }
    }

    #pragma unroll
    for (int p = 0; p < 3; p++) {
        if (p == 0)      { CP_WAIT(2); }
        else if (p == 1) { CP_WAIT(1); }
        else             { CP_WAIT(0); }
        __syncthreads();
        #pragma unroll
        for (int k4 = 0; k4 < 4; k4++) {
            int kk = p * 4 + k4;
            uint32_t bfr[4][2];
            #pragma unroll
            for (int h = 0; h < 2; h++) {
                uint32_t a = sb +
                    (uint32_t)((kk * 16 + (grp & 1) * 8 + lr8) * RKG) +
                    (uint32_t)(wn * 64 + h * 32 + (grp >> 1) * 16);
                uint32_t r[4];
                ldsm_x4_trans(r, a);
                bfr[2 * h][0] = r[0]; bfr[2 * h][1] = r[1];
                bfr[2 * h + 1][0] = r[2]; bfr[2 * h + 1][1] = r[3];
            }
            #pragma unroll
            for (int mt = 0; mt < 4; mt++) {
                int fidx = ((wm * 4 + mt) * 12 + kk) * 32 + lane;
                uint4 H = g_WfHi[fidx];
                uint32_t ah[4] = {H.x, H.y, H.z, H.w};
                #pragma unroll
                for (int nt = 0; nt < 4; nt++)
                    mma16816(acc[mt][nt], ah, bfr[nt]);
            }
        }
    }

    // LSTM epilogue + comb_{t+1} (single fp16)
    const int r = lane >> 2;
    const int q2 = (lane & 3) * 2;
    #pragma unroll
    for (int s = 0; s < 2; s++) {
        int c = wm * 16 + r + 8 * s;
        float bi = bias[c];
        float bf = bias[64 + c];
        float bg = bias[128 + c];
        float bo = bias[192 + c];
        #pragma unroll
        for (int nt = 0; nt < 4; nt++) {
            int v = v0 + wn * 32 + nt * 8 + q2;
            size_t idx = (size_t)b * CVSZ + (size_t)c * VV + v;
            float2 cold = *reinterpret_cast<const float2*>(g_c + idx);
            float i0 = acc[0][nt][2 * s]     + bi;
            float i1 = acc[0][nt][2 * s + 1] + bi;
            float f0 = acc[1][nt][2 * s]     + bf;
            float f1 = acc[1][nt][2 * s + 1] + bf;
            float g0 = acc[2][nt][2 * s]     + bg;
            float g1 = acc[2][nt][2 * s + 1] + bg;
            float o0 = acc[3][nt][2 * s]     + bo;
            float o1 = acc[3][nt][2 * s + 1] + bo;
            float cy0 = sigf(f0) * cold.x + sigf(i0) * g0;
            float cy1 = sigf(f1) * cold.y + sigf(i1) * g1;
            float hy0 = sigf(o0) * tanh_fast(cy0);
            float hy1 = sigf(o1) * tanh_fast(cy1);
            *reinterpret_cast<float2*>(g_c + idx)   = make_float2(cy0, cy1);
            *reinterpret_cast<float2*>(ysOut + idx) = make_float2(hy0, hy1);
            if (xnext) {
                float2 xv = *reinterpret_cast<const float2*>(xnext + idx);
                *reinterpret_cast<uint32_t*>(g_comb + idx) =
                    packh2(xv.x + hy0, xv.y + hy1);
            }
        }
    }
}

// ---------------------------------------------------------------------------
__global__ __launch_bounds__(256) void proj_out(const float* __restrict__ Wout,
                                                const float* __restrict__ bout,
                                                float* __restrict__ out) {
    __shared__ float sm[TT * CC * 8];
    int b  = blockIdx.y;
    int v0 = blockIdx.x * 8;
    for (int i = threadIdx.x; i < TT * CC * 8; i += 256) {
        int t = i / (CC * 8);
        int rem = i % (CC * 8);
        int c = rem >> 3, vv = rem & 7;
        sm[i] = g_ys[(size_t)t * PART + (size_t)b * CVSZ + (size_t)c * VV + v0 + vv];
    }
    __syncthreads();
    for (int p = threadIdx.x; p < COUT * 8; p += 256) {
        int o = p >> 3, vv = p & 7;
        float accp[TT];
        #pragma unroll
        for (int t = 0; t < TT; t++) accp[t] = 0.f;
        for (int c = 0; c < CC; c++) {
            float w = Wout[o * CC + c];
            #pragma unroll
            for (int t = 0; t < TT; t++) accp[t] += w * sm[t * (CC * 8) + c * 8 + vv];
        }
        float bo = bout[o];
        float* op = out + ((size_t)(b * COUT + o) * VV + v0 + vv) * TT;
        #pragma unroll
        for (int t = 0; t < TT; t++) op[t] = accp[t] + bo;
    }
}

// ---------------------------------------------------------------------------
extern "C" void kernel_launch(void* const* d_in, const int* in_sizes, int n_in,
                              void* d_out, int out_size) {
    const float* x      = (const float*)d_in[0];
    const float* Amat   = (const float*)d_in[1];
    const float* W_gout = (const float*)d_in[2];
    const float* b_gout = (const float*)d_in[3];
    const float* W_out  = (const float*)d_in[4];
    const float* b_out  = (const float*)d_in[5];
    float* out = (float*)d_out;

    float *xT, *ys;
    __half *bhi, *blo, *armhi, *armlo;
    cudaGetSymbolAddress((void**)&xT, g_xT);
    cudaGetSymbolAddress((void**)&ys, g_ys);
    cudaGetSymbolAddress((void**)&bhi,  g_Bhi);
    cudaGetSymbolAddress((void**)&blo,  g_Blo);
    cudaGetSymbolAddress((void**)&armhi, g_Armhi);
    cudaGetSymbolAddress((void**)&armlo, g_Armlo);

    cudaFuncSetAttribute(hop_setup, cudaFuncAttributeMaxDynamicSharedMemorySize, SETUP_SMEM);
    cudaFuncSetAttribute(hop_step,  cudaFuncAttributeMaxDynamicSharedMemorySize, HOP_SMEM);
    cudaFuncSetAttribute(gate_lstm, cudaFuncAttributeMaxDynamicSharedMemorySize, GATE_SMEM);

    transpose_x<<<dim3(MROWS, VV / 32), 256>>>(x);
    zero_c<<<(MROWS * VV) / 256, 256>>>();
    bsplit<<<dim3(32, 32), 256>>>(Amat);
    asplit<<<(VV * VV / 4) / 256, 256>>>(Amat);
    wfrag<<<16 * 12, 32>>>(W_gout);
    comb_init<<<(MROWS * VV / 4) / 256, 256>>>(xT);

    // Precompute (A^2)^T into B2 rows 1024..2047 (split-3 accuracy)
    const size_t VOFF = (size_t)VV * VV;
    hop_setup<<<dim3(8, 8), 256, SETUP_SMEM>>>(bhi, blo, armhi, armlo,
                                               bhi + VOFF, blo + VOFF);

    dim3 hopGrid(2 * VV / 128, MROWS / 128);   // (16, 16) = 256 CTAs, 2/SM
    dim3 gateGrid(VV / 64, BB);                // (16, 32) = 512 CTAs, 2/SM

    for (int t = 0; t < TT; t++) {
        hop_step<<<hopGrid, 256, HOP_SMEM>>>();   // [x1|x2] = comb @ [A|A^2] (hi only)
        const float* xnext = (t + 1 < TT) ? (xT + (size_t)(t + 1) * PART) : nullptr;
        gate_lstm<<<gateGrid, 256, GATE_SMEM>>>(b_gout, ys + (size_t)t * PART, xnext);
    }

    proj_out<<<dim3(VV / 8, BB), 256>>>(W_out, b_out, out);
}

// round 17
// speedup vs baseline: 1.0389x; 1.0389x over previous
#include <cuda_runtime.h>
#include <cuda_fp16.h>
#include <math.h>
#include <stdint.h>

// Problem constants
#define BB 32
#define CC 64
#define VV 1024
#define TT 24
#define COUT 64
#define MROWS (BB*CC)            // 2048
#define PART ((size_t)MROWS*VV)  // 2,097,152
#define CVSZ (CC*VV)             // 65536

// ---------------------------------------------------------------------------
__device__ __forceinline__ uint32_t smem_to_u32(const void* p) {
    uint32_t a;
    asm("{ .reg .u64 t; cvta.to.shared.u64 t, %1; cvt.u32.u64 %0, t; }" : "=r"(a) : "l"(p));
    return a;
}
__device__ __forceinline__ void cpasync16(uint32_t dst, const void* src) {
    asm volatile("cp.async.cg.shared.global [%0], [%1], 16;" :: "r"(dst), "l"(src));
}
#define CP_COMMIT() asm volatile("cp.async.commit_group;" ::: "memory")
#define CP_WAIT(n)  asm volatile("cp.async.wait_group %0;" :: "n"(n) : "memory")

__device__ __forceinline__ void ldsm_x4(uint32_t* r, uint32_t a) {
    asm volatile("ldmatrix.sync.aligned.m8n8.x4.shared.b16 {%0,%1,%2,%3}, [%4];"
                 : "=r"(r[0]), "=r"(r[1]), "=r"(r[2]), "=r"(r[3]) : "r"(a));
}
__device__ __forceinline__ void ldsm_x4_trans(uint32_t* r, uint32_t a) {
    asm volatile("ldmatrix.sync.aligned.m8n8.x4.trans.shared.b16 {%0,%1,%2,%3}, [%4];"
                 : "=r"(r[0]), "=r"(r[1]), "=r"(r[2]), "=r"(r[3]) : "r"(a));
}

// m16n8k16 row.col fp16 -> fp32 accumulate
__device__ __forceinline__ void mma16816(float* c, const uint32_t* a, const uint32_t* b) {
    asm volatile(
        "mma.sync.aligned.m16n8k16.row.col.f32.f16.f16.f32 "
        "{%0,%1,%2,%3}, {%4,%5,%6,%7}, {%8,%9}, {%0,%1,%2,%3};"
        : "+f"(c[0]), "+f"(c[1]), "+f"(c[2]), "+f"(c[3])
        : "r"(a[0]), "r"(a[1]), "r"(a[2]), "r"(a[3]), "r"(b[0]), "r"(b[1]));
}

__device__ __forceinline__ float sigf(float x) { return 1.0f / (1.0f + __expf(-x)); }
__device__ __forceinline__ float tanh_fast(float x) {
    float y; asm("tanh.approx.f32 %0, %1;" : "=f"(y) : "f"(x)); return y;
}
__device__ __forceinline__ uint32_t packh2(float a, float b) {
    return ((uint32_t)__half_as_ushort(__float2half_rn(b)) << 16) |
           (uint32_t)__half_as_ushort(__float2half_rn(a));
}
__device__ __forceinline__ float h2f(float a) {
    return __half2float(__float2half_rn(a));
}

// ---------------------------------------------------------------------------
// Scratch
__device__ __align__(128) __half g_xT[(size_t)TT*MROWS*VV];  // fp16 transport
__device__ __align__(128) __half g_ys[(size_t)TT*MROWS*VV];  // fp16 transport
__device__ __align__(128) float g_c[(size_t)MROWS*VV];
__device__ __align__(128) __half g_comb[(size_t)MROWS*VV];   // single fp16 plane
__device__ __align__(128) __half g_x1[(size_t)MROWS*VV];
__device__ __align__(128) __half g_x2[(size_t)MROWS*VV];
// B2 = [A^T ; (A^2)^T] fp16 hi (step hop uses hi ONLY), lo (setup only)
__device__ __align__(128) __half g_Bhi[(size_t)2*VV*VV];
__device__ __align__(128) __half g_Blo[(size_t)2*VV*VV];
// A row-major fp16 hi/lo (setup only)
__device__ __align__(128) __half g_Armhi[(size_t)VV*VV];
__device__ __align__(128) __half g_Armlo[(size_t)VV*VV];
// W prepacked per-lane mma A-fragments fp16 (hi only)
__device__ __align__(128) uint4 g_WfHi[16*12*32];

// ---------------------------------------------------------------------------
// Transpose x: (B,C,V,T) fp32 -> xT (T, B*C, V) fp16.
__global__ void transpose_x(const float* __restrict__ x) {
    __shared__ float tile[32][25];
    int r  = blockIdx.x;
    int v0 = blockIdx.y * 32;
    const float* src = x + ((size_t)r * VV + v0) * TT;
    for (int i = threadIdx.x; i < 32 * TT; i += blockDim.x) {
        int v = i / TT, t = i % TT;
        tile[v][t] = src[i];
    }
    __syncthreads();
    for (int i = threadIdx.x; i < 32 * TT; i += blockDim.x) {
        int t = i / 32, v = i % 32;
        g_xT[(size_t)t * PART + (size_t)r * VV + v0 + v] = __float2half_rn(tile[v][t]);
    }
}

__global__ void zero_c() {
    size_t i = (size_t)blockIdx.x * blockDim.x + threadIdx.x;
    g_c[i] = 0.0f;
}

// Bhi/Blo[n][k] = fp16split(A[k][n])  (rows 0..1023 of B2)
__global__ void bsplit(const float* __restrict__ A) {
    __shared__ float tile[32][33];
    int k0 = blockIdx.x * 32, n0 = blockIdx.y * 32;
    int tx = threadIdx.x & 31, ty = threadIdx.x >> 5;
    #pragma unroll
    for (int i = 0; i < 4; i++) {
        int k = ty + i * 8;
        tile[k][tx] = A[(size_t)(k0 + k) * VV + n0 + tx];
    }
    __syncthreads();
    #pragma unroll
    for (int i = 0; i < 4; i++) {
        int n = ty + i * 8;
        float v = tile[tx][n];
        __half h = __float2half_rn(v);
        __half l = __float2half_rn(v - __half2float(h));
        g_Bhi[(size_t)(n0 + n) * VV + k0 + tx] = h;
        g_Blo[(size_t)(n0 + n) * VV + k0 + tx] = l;
    }
}

// A row-major fp16 hi/lo
__global__ void asplit(const float* __restrict__ A) {
    size_t i = ((size_t)blockIdx.x * blockDim.x + threadIdx.x) * 4;
    float4 v = *reinterpret_cast<const float4*>(A + i);
    *reinterpret_cast<uint2*>(g_Armhi + i) =
        make_uint2(packh2(v.x, v.y), packh2(v.z, v.w));
    *reinterpret_cast<uint2*>(g_Armlo + i) =
        make_uint2(packh2(v.x - h2f(v.x), v.y - h2f(v.y)),
                   packh2(v.z - h2f(v.z), v.w - h2f(v.w)));
}

// Prepack W into per-lane mma A-fragments (fp16 hi plane).
__global__ void wfrag(const float* __restrict__ W) {
    int tile = blockIdx.x;
    int lane = threadIdx.x;
    int tileM = tile / 12, tileK = tile % 12;
    int r = lane >> 2, c2 = (lane & 3) * 2;

    auto getw = [&](int pr, int k) -> float {
        int wm = pr >> 6, g = (pr >> 4) & 3, cl = pr & 15;
        int o = g * 64 + wm * 16 + cl;
        return W[(size_t)o * 192 + k];
    };
    int p0 = tileM * 16 + r, k0 = tileK * 16 + c2;
    float w[4][2];
    w[0][0] = getw(p0,     k0);     w[0][1] = getw(p0,     k0 + 1);
    w[1][0] = getw(p0 + 8, k0);     w[1][1] = getw(p0 + 8, k0 + 1);
    w[2][0] = getw(p0,     k0 + 8); w[2][1] = getw(p0,     k0 + 9);
    w[3][0] = getw(p0 + 8, k0 + 8); w[3][1] = getw(p0 + 8, k0 + 9);

    uint32_t hi[4];
    #pragma unroll
    for (int q = 0; q < 4; q++)
        hi[q] = packh2(w[q][0], w[q][1]);
    g_WfHi[tile * 32 + lane] = make_uint4(hi[0], hi[1], hi[2], hi[3]);
}

// comb init for t=0: comb = x0 (h = 0) — straight copy (xT already fp16)
__global__ void comb_init() {
    size_t i = ((size_t)blockIdx.x * blockDim.x + threadIdx.x) * 8;
    *reinterpret_cast<uint4*>(g_comb + i) = *reinterpret_cast<const uint4*>(g_xT + i);
}

// ---------------------------------------------------------------------------
// Setup GEMM (A^2 precompute) — fp16 split-3, writes hi/lo output.
#define ROWB 80
#define HPLANE (128*ROWB)            // 10240
#define HBUF4 (4*HPLANE)             // 40960
#define SETUP_SMEM (2*HBUF4)         // 81920

__global__ __launch_bounds__(256, 1) void hop_setup(
    const __half* __restrict__ Ahi, const __half* __restrict__ Alo,
    const __half* __restrict__ Bhi, const __half* __restrict__ Blo,
    __half* __restrict__ Chi, __half* __restrict__ Clo)
{
    extern __shared__ char smem[];
    uint32_t sb = smem_to_u32(smem);
    const int tid = threadIdx.x, lane = tid & 31, wid = tid >> 5;
    const int wm = wid & 3, wn = wid >> 2;
    const int m0 = blockIdx.y * 128, n0 = blockIdx.x * 128;
    const int lr  = lane >> 2;

    float acc[2][8][4];
    #pragma unroll
    for (int mt = 0; mt < 2; mt++)
        #pragma unroll
        for (int nt = 0; nt < 8; nt++)
            #pragma unroll
            for (int q = 0; q < 4; q++) acc[mt][nt][q] = 0.f;

    const int gr = tid >> 2, gc = tid & 3;

    auto load_chunk = [&](int k0, uint32_t base) {
        #pragma unroll
        for (int it = 0; it < 2; it++) {
            int row = gr + it * 64;
            uint32_t doff = (uint32_t)(row * ROWB + gc * 16);
            size_t ga = (((size_t)(m0 + row)) << 10) + k0 + gc * 8;
            size_t gb = (((size_t)(n0 + row)) << 10) + k0 + gc * 8;
            cpasync16(base + doff,              Ahi + ga);
            cpasync16(base + HPLANE + doff,     Alo + ga);
            cpasync16(base + 2 * HPLANE + doff, Bhi + gb);
            cpasync16(base + 3 * HPLANE + doff, Blo + gb);
        }
        CP_COMMIT();
    };

    load_chunk(0, sb);

    const uint32_t aRowSel = (uint32_t)(lane & 15);
    const uint32_t aColSel = (uint32_t)((lane >> 4) * 16);
    const uint32_t bRowSel = (uint32_t)(((lane >> 4) << 3) + (lane & 7));
    const uint32_t bColSel = (uint32_t)(((lane >> 3) & 1) * 16);

    for (int chunk = 0; chunk < 32; chunk++) {
        uint32_t base = sb + (chunk & 1) * HBUF4;
        if (chunk + 1 < 32) {
            load_chunk((chunk + 1) * 32, sb + ((chunk + 1) & 1) * HBUF4);
            CP_WAIT(1);
        } else {
            CP_WAIT(0);
        }
        __syncthreads();

        uint32_t aB = base + (uint32_t)(wm * 32) * ROWB;
        uint32_t bB = base + 2 * HPLANE + (uint32_t)(wn * 64) * ROWB;
        #pragma unroll
        for (int ks = 0; ks < 2; ks++) {
            uint32_t koff = (uint32_t)(ks * 32);
            uint32_t ah[2][4], al[2][4];
            #pragma unroll
            for (int mt = 0; mt < 2; mt++) {
                uint32_t a = aB + (uint32_t)(mt * 16 + aRowSel) * ROWB + koff + aColSel;
                ldsm_x4(ah[mt], a);
                ldsm_x4(al[mt], a + HPLANE);
            }
            #pragma unroll
            for (int h = 0; h < 4; h++) {
                uint32_t a = bB + (uint32_t)(h * 16 + bRowSel) * ROWB + koff + bColSel;
                uint32_t rh[4], rl[4];
                ldsm_x4(rh, a);
                ldsm_x4(rl, a + HPLANE);
                uint32_t b0h[2] = {rh[0], rh[1]}, b1h[2] = {rh[2], rh[3]};
                uint32_t b0l[2] = {rl[0], rl[1]}, b1l[2] = {rl[2], rl[3]};
                #pragma unroll
                for (int mt = 0; mt < 2; mt++) {
                    mma16816(acc[mt][2*h],   ah[mt], b0h);
                    mma16816(acc[mt][2*h],   ah[mt], b0l);
                    mma16816(acc[mt][2*h],   al[mt], b0h);
                    mma16816(acc[mt][2*h+1], ah[mt], b1h);
                    mma16816(acc[mt][2*h+1], ah[mt], b1l);
                    mma16816(acc[mt][2*h+1], al[mt], b1h);
                }
            }
        }
        __syncthreads();
    }

    #pragma unroll
    for (int mt = 0; mt < 2; mt++) {
        int row = m0 + wm * 32 + mt * 16 + lr;
        #pragma unroll
        for (int nt = 0; nt < 8; nt++) {
            int col = n0 + wn * 64 + nt * 8 + (lane & 3) * 2;
            float v0 = acc[mt][nt][0], v1 = acc[mt][nt][1];
            float v2 = acc[mt][nt][2], v3 = acc[mt][nt][3];
            size_t o0 = (size_t)row * 1024 + col;
            size_t o1 = (size_t)(row + 8) * 1024 + col;
            *reinterpret_cast<uint32_t*>(Chi + o0) = packh2(v0, v1);
            *reinterpret_cast<uint32_t*>(Chi + o1) = packh2(v2, v3);
            *reinterpret_cast<uint32_t*>(Clo + o0) = packh2(v0 - h2f(v0), v1 - h2f(v1));
            *reinterpret_cast<uint32_t*>(Clo + o1) = packh2(v2 - h2f(v2), v3 - h2f(v3));
        }
    }
}

// ---------------------------------------------------------------------------
// Step hop GEMM: [x1|x2] = comb(fp16) @ B2hi(fp16) — single product.
// R15-proven: 2-stage double buffer, 2 CTAs/SM.
#define SBUF (2*HPLANE)              // 20480: [A | Bhi]
#define HOP_SMEM (2*SBUF)            // 40960

__global__ __launch_bounds__(256, 2) void hop_step()
{
    extern __shared__ char smem[];
    uint32_t sb = smem_to_u32(smem);
    const int tid = threadIdx.x, lane = tid & 31, wid = tid >> 5;
    const int wm = wid & 3, wn = wid >> 2;          // warp tile: M32 x N64
    const int m0 = blockIdx.y * 128, n0 = blockIdx.x * 128;  // n over 2048
    const int lr  = lane >> 2;

    float acc[2][8][4];
    #pragma unroll
    for (int mt = 0; mt < 2; mt++)
        #pragma unroll
        for (int nt = 0; nt < 8; nt++)
            #pragma unroll
            for (int q = 0; q < 4; q++) acc[mt][nt][q] = 0.f;

    const int gr = tid >> 2, gc = tid & 3;

    auto load_chunk = [&](int k0, uint32_t base) {
        #pragma unroll
        for (int it = 0; it < 2; it++) {
            int row = gr + it * 64;
            uint32_t doff = (uint32_t)(row * ROWB + gc * 16);
            size_t ga = (((size_t)(m0 + row)) << 10) + k0 + gc * 8;
            size_t gb = (((size_t)(n0 + row)) << 10) + k0 + gc * 8;
            cpasync16(base + doff,          g_comb + ga);
            cpasync16(base + HPLANE + doff, g_Bhi + gb);
        }
        CP_COMMIT();
    };

    load_chunk(0, sb);

    const uint32_t aRowSel = (uint32_t)(lane & 15);
    const uint32_t aColSel = (uint32_t)((lane >> 4) * 16);
    const uint32_t bRowSel = (uint32_t)(((lane >> 4) << 3) + (lane & 7));
    const uint32_t bColSel = (uint32_t)(((lane >> 3) & 1) * 16);

    for (int chunk = 0; chunk < 32; chunk++) {
        uint32_t base = sb + (chunk & 1) * SBUF;
        if (chunk + 1 < 32) {
            load_chunk((chunk + 1) * 32, sb + ((chunk + 1) & 1) * SBUF);
            CP_WAIT(1);
        } else {
            CP_WAIT(0);
        }
        __syncthreads();

        uint32_t aB = base + (uint32_t)(wm * 32) * ROWB;
        uint32_t bB = base + HPLANE + (uint32_t)(wn * 64) * ROWB;
        #pragma unroll
        for (int ks = 0; ks < 2; ks++) {
            uint32_t koff = (uint32_t)(ks * 32);
            uint32_t ah[2][4];
            #pragma unroll
            for (int mt = 0; mt < 2; mt++) {
                uint32_t a = aB + (uint32_t)(mt * 16 + aRowSel) * ROWB + koff + aColSel;
                ldsm_x4(ah[mt], a);
            }
            #pragma unroll
            for (int h = 0; h < 4; h++) {
                uint32_t a = bB + (uint32_t)(h * 16 + bRowSel) * ROWB + koff + bColSel;
                uint32_t rh[4];
                ldsm_x4(rh, a);
                uint32_t b0h[2] = {rh[0], rh[1]}, b1h[2] = {rh[2], rh[3]};
                #pragma unroll
                for (int mt = 0; mt < 2; mt++) {
                    mma16816(acc[mt][2*h],   ah[mt], b0h);
                    mma16816(acc[mt][2*h+1], ah[mt], b1h);
                }
            }
        }
        __syncthreads();
    }

    // Epilogue: single fp16 plane; n0<1024 -> x1, else x2
    __half* Cout = (n0 < 1024) ? g_x1 : g_x2;
    const int nb = n0 & 1023;
    #pragma unroll
    for (int mt = 0; mt < 2; mt++) {
        int row = m0 + wm * 32 + mt * 16 + lr;
        #pragma unroll
        for (int nt = 0; nt < 8; nt++) {
            int col = nb + wn * 64 + nt * 8 + (lane & 3) * 2;
            size_t o0 = (size_t)row * 1024 + col;
            size_t o1 = (size_t)(row + 8) * 1024 + col;
            *reinterpret_cast<uint32_t*>(Cout + o0) = packh2(acc[mt][nt][0], acc[mt][nt][1]);
            *reinterpret_cast<uint32_t*>(Cout + o1) = packh2(acc[mt][nt][2], acc[mt][nt][3]);
        }
    }
}

// ---------------------------------------------------------------------------
// Gate GEMM (W hi-only fp16 frags x G single fp16) + LSTM + comb_{t+1}.
// R15-proven bulk load. ys and xnext now fp16.
#define RKG 144
#define GATE_SMEM (192*RKG)          // 27648

__global__ __launch_bounds__(256, 2) void gate_lstm(
    const float* __restrict__ bias, __half* __restrict__ ysOut,
    const __half* __restrict__ xnext)
{
    extern __shared__ char smem[];
    uint32_t sb = smem_to_u32(smem);
    const int tid = threadIdx.x, lane = tid & 31, wid = tid >> 5;
    const int wm = wid & 3, wn = wid >> 2;       // warp tile M64 x N32
    const int v0 = blockIdx.x * 64;
    const int b  = blockIdx.y;
    const int grp = lane >> 3, lr8 = lane & 7;

    float acc[4][4][4];
    #pragma unroll
    for (int mt = 0; mt < 4; mt++)
        #pragma unroll
        for (int nt = 0; nt < 4; nt++)
            #pragma unroll
            for (int q = 0; q < 4; q++) acc[mt][nt][q] = 0.f;

    // Load all 192 G rows (comb | x1 | x2) for (b, v-strip) upfront
    {
        #pragma unroll
        for (int j = 0; j < 6; j++) {
            int idx = tid + j * 256;
            int row = idx >> 3, i8 = idx & 7;
            int p = row >> 6, c = row & 63;
            const __half* src = (p == 0) ? g_comb : (p == 1) ? g_x1 : g_x2;
            size_t gsrc = (((size_t)(b * 64 + c)) << 10) + v0 + i8 * 8;
            cpasync16(sb + (uint32_t)(row * RKG + i8 * 16), src + gsrc);
        }
        CP_COMMIT();
    }
    CP_WAIT(0);
    __syncthreads();

    #pragma unroll
    for (int kk = 0; kk < 12; kk++) {
        uint32_t bfr[4][2];
        #pragma unroll
        for (int h = 0; h < 2; h++) {
            uint32_t a = sb +
                (uint32_t)((kk * 16 + (grp & 1) * 8 + lr8) * RKG) +
                (uint32_t)(wn * 64 + h * 32 + (grp >> 1) * 16);
            uint32_t r[4];
            ldsm_x4_trans(r, a);
            bfr[2 * h][0] = r[0]; bfr[2 * h][1] = r[1];
            bfr[2 * h + 1][0] = r[2]; bfr[2 * h + 1][1] = r[3];
        }
        #pragma unroll
        for (int mt = 0; mt < 4; mt++) {
            int fidx = ((wm * 4 + mt) * 12 + kk) * 32 + lane;
            uint4 H = g_WfHi[fidx];
            uint32_t ah[4] = {H.x, H.y, H.z, H.w};
            #pragma unroll
            for (int nt = 0; nt < 4; nt++)
                mma16816(acc[mt][nt], ah, bfr[nt]);
        }
    }

    // LSTM epilogue + comb_{t+1} (single fp16); ys written as fp16
    const int r = lane >> 2;
    const int q2 = (lane & 3) * 2;
    #pragma unroll
    for (int s = 0; s < 2; s++) {
        int c = wm * 16 + r + 8 * s;
        float bi = bias[c];
        float bf = bias[64 + c];
        float bg = bias[128 + c];
        float bo = bias[192 + c];
        #pragma unroll
        for (int nt = 0; nt < 4; nt++) {
            int v = v0 + wn * 32 + nt * 8 + q2;
            size_t idx = (size_t)b * CVSZ + (size_t)c * VV + v;
            float2 cold = *reinterpret_cast<const float2*>(g_c + idx);
            float i0 = acc[0][nt][2 * s]     + bi;
            float i1 = acc[0][nt][2 * s + 1] + bi;
            float f0 = acc[1][nt][2 * s]     + bf;
            float f1 = acc[1][nt][2 * s + 1] + bf;
            float g0 = acc[2][nt][2 * s]     + bg;
            float g1 = acc[2][nt][2 * s + 1] + bg;
            float o0 = acc[3][nt][2 * s]     + bo;
            float o1 = acc[3][nt][2 * s + 1] + bo;
            float cy0 = sigf(f0) * cold.x + sigf(i0) * g0;
            float cy1 = sigf(f1) * cold.y + sigf(i1) * g1;
            float hy0 = sigf(o0) * tanh_fast(cy0);
            float hy1 = sigf(o1) * tanh_fast(cy1);
            *reinterpret_cast<float2*>(g_c + idx)    = make_float2(cy0, cy1);
            *reinterpret_cast<uint32_t*>(ysOut + idx) = packh2(hy0, hy1);
            if (xnext) {
                uint32_t xu = *reinterpret_cast<const uint32_t*>(xnext + idx);
                __half2 xh = *reinterpret_cast<const __half2*>(&xu);
                *reinterpret_cast<uint32_t*>(g_comb + idx) =
                    packh2(__half2float(xh.x) + hy0, __half2float(xh.y) + hy1);
            }
        }
    }
}

// ---------------------------------------------------------------------------
// Final projection: ys now fp16.
__global__ __launch_bounds__(256) void proj_out(const float* __restrict__ Wout,
                                                const float* __restrict__ bout,
                                                float* __restrict__ out) {
    __shared__ float sm[TT * CC * 8];
    int b  = blockIdx.y;
    int v0 = blockIdx.x * 8;
    for (int i = threadIdx.x; i < TT * CC * 8; i += 256) {
        int t = i / (CC * 8);
        int rem = i % (CC * 8);
        int c = rem >> 3, vv = rem & 7;
        sm[i] = __half2float(
            g_ys[(size_t)t * PART + (size_t)b * CVSZ + (size_t)c * VV + v0 + vv]);
    }
    __syncthreads();
    for (int p = threadIdx.x; p < COUT * 8; p += 256) {
        int o = p >> 3, vv = p & 7;
        float accp[TT];
        #pragma unroll
        for (int t = 0; t < TT; t++) accp[t] = 0.f;
        for (int c = 0; c < CC; c++) {
            float w = Wout[o * CC + c];
            #pragma unroll
            for (int t = 0; t < TT; t++) accp[t] += w * sm[t * (CC * 8) + c * 8 + vv];
        }
        float bo = bout[o];
        float* op = out + ((size_t)(b * COUT + o) * VV + v0 + vv) * TT;
        #pragma unroll
        for (int t = 0; t < TT; t++) op[t] = accp[t] + bo;
    }
}

// ---------------------------------------------------------------------------
extern "C" void kernel_launch(void* const* d_in, const int* in_sizes, int n_in,
                              void* d_out, int out_size) {
    const float* x      = (const float*)d_in[0];
    const float* Amat   = (const float*)d_in[1];
    const float* W_gout = (const float*)d_in[2];
    const float* b_gout = (const float*)d_in[3];
    const float* W_out  = (const float*)d_in[4];
    const float* b_out  = (const float*)d_in[5];
    float* out = (float*)d_out;

    __half *xT, *ys, *bhi, *blo, *armhi, *armlo;
    cudaGetSymbolAddress((void**)&xT, g_xT);
    cudaGetSymbolAddress((void**)&ys, g_ys);
    cudaGetSymbolAddress((void**)&bhi,  g_Bhi);
    cudaGetSymbolAddress((void**)&blo,  g_Blo);
    cudaGetSymbolAddress((void**)&armhi, g_Armhi);
    cudaGetSymbolAddress((void**)&armlo, g_Armlo);

    cudaFuncSetAttribute(hop_setup, cudaFuncAttributeMaxDynamicSharedMemorySize, SETUP_SMEM);
    cudaFuncSetAttribute(hop_step,  cudaFuncAttributeMaxDynamicSharedMemorySize, HOP_SMEM);
    cudaFuncSetAttribute(gate_lstm, cudaFuncAttributeMaxDynamicSharedMemorySize, GATE_SMEM);

    transpose_x<<<dim3(MROWS, VV / 32), 256>>>(x);
    zero_c<<<(MROWS * VV) / 256, 256>>>();
    bsplit<<<dim3(32, 32), 256>>>(Amat);
    asplit<<<(VV * VV / 4) / 256, 256>>>(Amat);
    wfrag<<<16 * 12, 32>>>(W_gout);
    comb_init<<<(MROWS * VV / 8) / 256, 256>>>();

    // Precompute (A^2)^T into B2 rows 1024..2047 (split-3 accuracy)
    const size_t VOFF = (size_t)VV * VV;
    hop_setup<<<dim3(8, 8), 256, SETUP_SMEM>>>(bhi, blo, armhi, armlo,
                                               bhi + VOFF, blo + VOFF);

    dim3 hopGrid(2 * VV / 128, MROWS / 128);   // (16, 16) = 256 CTAs, 2/SM
    dim3 gateGrid(VV / 64, BB);                // (16, 32) = 512 CTAs, 2/SM

    for (int t = 0; t < TT; t++) {
        hop_step<<<hopGrid, 256, HOP_SMEM>>>();   // [x1|x2] = comb @ [A|A^2] (hi only)
        const __half* xnext = (t + 1 < TT) ? (xT + (size_t)(t + 1) * PART) : nullptr;
        gate_lstm<<<gateGrid, 256, GATE_SMEM>>>(b_gout, ys + (size_t)t * PART, xnext);
    }

    proj_out<<<dim3(VV / 8, BB), 256>>>(W_out, b_out, out);
}